// round 1
// baseline (speedup 1.0000x reference)
#include <cuda_runtime.h>
#include <cstdint>

#define BT 131072   // B*T = 256*512
#define TT 512

// ---------------- scratch (device globals; no runtime allocation) ----------
__device__ float g_bufG[67108864];   // [BT,512]  G1 / G2 / Gd2 (reused)
__device__ float g_h1[16777216];    // [BT,128]
__device__ float g_d1[8388608];     // [BT,64]
__device__ float g_d2[16777216];    // [BT,128]
__device__ float g_z[16384];        // [256,64]
__device__ float g_gd1[65536];      // [256,256]

// ---------------- helpers ---------------------------------------------------
__device__ __forceinline__ void cp_async16(void* smem_dst, const void* gmem_src) {
    uint32_t s = (uint32_t)__cvta_generic_to_shared(smem_dst);
    asm volatile("cp.async.cg.shared.global [%0], [%1], 16;\n" :: "r"(s), "l"(gmem_src));
}
__device__ __forceinline__ void cp_async_commit() { asm volatile("cp.async.commit_group;\n"); }
__device__ __forceinline__ void cp_async_wait0()  { asm volatile("cp.async.wait_group 0;\n"); }

__device__ __forceinline__ void cluster_sync_() {
    asm volatile("barrier.cluster.arrive.aligned;\n" ::: "memory");
    asm volatile("barrier.cluster.wait.aligned;\n" ::: "memory");
}
__device__ __forceinline__ void st_remote_f32(float* local_ptr, uint32_t peer_rank, float v) {
    uint32_t la = (uint32_t)__cvta_generic_to_shared(local_ptr);
    uint32_t ra;
    asm volatile("mapa.shared::cluster.u32 %0, %1, %2;\n" : "=r"(ra) : "r"(la), "r"(peer_rank));
    asm volatile("st.shared::cluster.f32 [%0], %1;\n" :: "r"(ra), "f"(v) : "memory");
}
__device__ __forceinline__ float sigmoidf_(float x) {
    return 1.0f / (1.0f + __expf(-x));
}

// ---------------- bulk GEMM: C[M,N] = A[M,K] @ W[K,N] + bias ----------------
// 64x64 tile, BK=16, 256 threads, 4x4 per thread. M%64==0, N%64==0, K%16==0.
__global__ void gemm_bias_kernel(const float* __restrict__ A,
                                 const float* __restrict__ W,
                                 const float* __restrict__ bias,
                                 float* __restrict__ C,
                                 int M, int N, int K) {
    __shared__ float As[16][65];
    __shared__ float Bs[16][64];
    int tid = threadIdx.x;
    int m0 = blockIdx.x * 64, n0 = blockIdx.y * 64;
    int tm = (tid >> 4) * 4, tn = (tid & 15) * 4;
    int ar = tid >> 2, ak = (tid & 3) * 4;
    int bk = tid >> 4, bn = (tid & 15) * 4;
    float acc[4][4];
#pragma unroll
    for (int i = 0; i < 4; i++)
#pragma unroll
        for (int j = 0; j < 4; j++) acc[i][j] = 0.f;

    for (int kt = 0; kt < K; kt += 16) {
        float4 av = *(const float4*)(A + (size_t)(m0 + ar) * K + kt + ak);
        float4 bv = *(const float4*)(W + (size_t)(kt + bk) * N + n0 + bn);
        __syncthreads();
        As[ak + 0][ar] = av.x;
        As[ak + 1][ar] = av.y;
        As[ak + 2][ar] = av.z;
        As[ak + 3][ar] = av.w;
        *(float4*)&Bs[bk][bn] = bv;
        __syncthreads();
#pragma unroll
        for (int k = 0; k < 16; k++) {
            float a0 = As[k][tm + 0], a1 = As[k][tm + 1], a2 = As[k][tm + 2], a3 = As[k][tm + 3];
            float4 b = *(const float4*)&Bs[k][tn];
            acc[0][0] += a0 * b.x; acc[0][1] += a0 * b.y; acc[0][2] += a0 * b.z; acc[0][3] += a0 * b.w;
            acc[1][0] += a1 * b.x; acc[1][1] += a1 * b.y; acc[1][2] += a1 * b.z; acc[1][3] += a1 * b.w;
            acc[2][0] += a2 * b.x; acc[2][1] += a2 * b.y; acc[2][2] += a2 * b.z; acc[2][3] += a2 * b.w;
            acc[3][0] += a3 * b.x; acc[3][1] += a3 * b.y; acc[3][2] += a3 * b.z; acc[3][3] += a3 * b.w;
        }
    }
    float4 bb = *(const float4*)(bias + n0 + tn);
#pragma unroll
    for (int i = 0; i < 4; i++) {
        float4 o;
        o.x = acc[i][0] + bb.x;
        o.y = acc[i][1] + bb.y;
        o.z = acc[i][2] + bb.z;
        o.w = acc[i][3] + bb.w;
        *(float4*)(C + (size_t)(m0 + tm + i) * N + n0 + tn) = o;
    }
}

// ---------------- LSTM recurrence, H=64 (encoder L2 / decoder L1) -----------
// grid = 128 CTAs x 256 threads, each CTA owns 2 batch rows for all T steps.
// SMEM (floats): Wr_s[64][256]=16384 | z_s[256][2]=512 | h_s[2][2][64]=256 | gbuf[2][2][256]=1024
__global__ void lstm64_kernel(const float* __restrict__ gproj, // [BT,256] or [256,256] if constProj
                              const float* __restrict__ Wr,    // [64,256]
                              float* __restrict__ hseq,        // [BT,64] or null
                              float* __restrict__ hlast,       // [256,64] or null
                              int constProj) {
    extern __shared__ float sm[];
    float (*Wr_s)[256] = (float (*)[256])sm;
    float (*z_s)[2] = (float (*)[2])(sm + 16384);
    float* h_s = sm + 16384 + 512;     // [buf][r][j] = buf*128 + r*64 + j
    float* gbuf = h_s + 256;           // [buf][r][n] = buf*512 + r*256 + n

    int tid = threadIdx.x;
    int b0 = blockIdx.x * 2;

    // load Wr (16384 floats) as float4
    for (int i = tid; i < 4096; i += 256)
        ((float4*)sm)[i] = ((const float4*)Wr)[i];
    if (tid < 128) h_s[tid] = 0.f;     // h_s[0][*][*]

    float c = 0.f;
    int r2 = (tid >> 6) & 1, j2 = tid & 63;

    // preload gproj for t=0
    if (tid < 128) {
        int r = tid >> 6, c4 = (tid & 63) * 4;
        const float* src = constProj ? (gproj + (size_t)(b0 + r) * 256 + c4)
                                     : (gproj + ((size_t)(b0 + r) * TT + 0) * 256 + c4);
        cp_async16(&gbuf[r * 256 + c4], src);
    }
    cp_async_commit();
    cp_async_wait0();
    __syncthreads();

    int p = 0, gb = 0;
    for (int t = 0; t < TT; t++) {
        if (!constProj && (t + 1) < TT && tid < 128) {
            int r = tid >> 6, c4 = (tid & 63) * 4;
            cp_async16(&gbuf[(gb ^ 1) * 512 + r * 256 + c4],
                       gproj + ((size_t)(b0 + r) * TT + (t + 1)) * 256 + c4);
        }
        cp_async_commit();

        // phase 1: z[r][tid] = gproj + h(t-1) @ Wr
        float acc0 = gbuf[gb * 512 + tid];
        float acc1 = gbuf[gb * 512 + 256 + tid];
        const float* hp = h_s + p * 128;
#pragma unroll
        for (int k = 0; k < 64; k += 4) {
            float4 h0 = *(const float4*)(hp + k);
            float4 h1 = *(const float4*)(hp + 64 + k);
            float w0 = Wr_s[k + 0][tid], w1 = Wr_s[k + 1][tid];
            float w2 = Wr_s[k + 2][tid], w3 = Wr_s[k + 3][tid];
            acc0 += w0 * h0.x; acc0 += w1 * h0.y; acc0 += w2 * h0.z; acc0 += w3 * h0.w;
            acc1 += w0 * h1.x; acc1 += w1 * h1.y; acc1 += w2 * h1.z; acc1 += w3 * h1.w;
        }
        z_s[tid][0] = acc0;
        z_s[tid][1] = acc1;
        __syncthreads();

        // phase 2: elementwise gate update (threads 0..127 own (r,j) pairs)
        if (tid < 128) {
            float zi = z_s[j2][r2];
            float zf = z_s[64 + j2][r2];
            float zg = z_s[128 + j2][r2];
            float zo = z_s[192 + j2][r2];
            float ig = sigmoidf_(zi);
            float fg = sigmoidf_(zf);
            float og = sigmoidf_(zo);
            float gg = fmaxf(zg, 0.f);
            c = fg * c + ig * gg;
            float h = og * fmaxf(c, 0.f);
            h_s[(p ^ 1) * 128 + r2 * 64 + j2] = h;
            if (hseq) hseq[((size_t)(b0 + r2) * TT + t) * 64 + j2] = h;
        }
        cp_async_wait0();
        __syncthreads();
        p ^= 1;
        if (!constProj) gb ^= 1;
    }
    if (hlast && tid < 128)
        hlast[(size_t)(b0 + r2) * 64 + j2] = h_s[p * 128 + r2 * 64 + j2];
}

// ---------------- LSTM recurrence, H=128 (encoder L1 / decoder L2) ----------
// 2-CTA cluster: each CTA holds half of Wr (its 64 h-indices x 4 gates = 256
// of the 512 gate columns, 128KB) and 4 batch rows. Per step it computes its
// half of h(t) and pushes it to the peer's SMEM via DSMEM, then cluster-syncs.
// SMEM (floats): Wr_s[128][256]=32768 | z_s[256][5]=1280 | h_s[2][4][128]=1024 | gbuf[2][4][256]=2048
__global__ void __cluster_dims__(2, 1, 1)
lstm128_kernel(const float* __restrict__ gproj, // [BT,512]
               const float* __restrict__ Wr,    // [128,512]
               float* __restrict__ hseq) {      // [BT,128]
    extern __shared__ float sm[];
    float (*Wr_s)[256] = (float (*)[256])sm;
    float (*z_s)[5] = (float (*)[5])(sm + 32768);
    float* h_s = sm + 32768 + 1280;   // [buf][r][j] = buf*512 + r*128 + j
    float* gbuf = h_s + 1024;         // [buf][r][n] = buf*1024 + r*256 + n

    int tid = threadIdx.x;
    uint32_t q;
    asm("mov.u32 %0, %%cluster_ctarank;" : "=r"(q));
    uint32_t peer = q ^ 1u;
    int cid = blockIdx.x >> 1;
    int b0 = cid * 4;

    // load Wr slice: n_local -> global gate column (n>>6)*128 + q*64 + (n&63)
    for (int i = tid; i < 128 * 256; i += 256) {
        int k = i >> 8, n = i & 255;
        int col = (n >> 6) * 128 + (int)q * 64 + (n & 63);
        Wr_s[k][n] = Wr[(size_t)k * 512 + col];
    }
    for (int i = tid; i < 512; i += 256) h_s[i] = 0.f;  // h_s[0][*][*]

    float c = 0.f;
    int r2 = tid >> 6;       // 0..3 (phase-2 row)
    int jj = tid & 63;       // phase-2 local h-index
    int jg = (int)q * 64 + jj;

    // gbuf copy mapping (all 256 threads, one float4 each)
    int pr = tid >> 6, pt4 = (tid & 63) * 4;
    int pcol = (pt4 >> 6) * 128 + (int)q * 64 + (pt4 & 63);

    // preload t=0
    cp_async16(&gbuf[pr * 256 + pt4],
               gproj + ((size_t)(b0 + pr) * TT + 0) * 512 + pcol);
    cp_async_commit();
    cp_async_wait0();
    __syncthreads();

    int p = 0, gb = 0;
    for (int t = 0; t < TT; t++) {
        if ((t + 1) < TT)
            cp_async16(&gbuf[(gb ^ 1) * 1024 + pr * 256 + pt4],
                       gproj + ((size_t)(b0 + pr) * TT + (t + 1)) * 512 + pcol);
        cp_async_commit();

        // phase 1: thread computes z for its gate column, 4 batch rows
        float acc0 = gbuf[gb * 1024 + tid];
        float acc1 = gbuf[gb * 1024 + 256 + tid];
        float acc2 = gbuf[gb * 1024 + 512 + tid];
        float acc3 = gbuf[gb * 1024 + 768 + tid];
        const float* hp = h_s + p * 512;
#pragma unroll 8
        for (int k = 0; k < 128; k += 4) {
            float4 h0 = *(const float4*)(hp + k);
            float4 h1 = *(const float4*)(hp + 128 + k);
            float4 h2 = *(const float4*)(hp + 256 + k);
            float4 h3 = *(const float4*)(hp + 384 + k);
            float w0 = Wr_s[k + 0][tid], w1 = Wr_s[k + 1][tid];
            float w2 = Wr_s[k + 2][tid], w3 = Wr_s[k + 3][tid];
            acc0 += w0 * h0.x; acc0 += w1 * h0.y; acc0 += w2 * h0.z; acc0 += w3 * h0.w;
            acc1 += w0 * h1.x; acc1 += w1 * h1.y; acc1 += w2 * h1.z; acc1 += w3 * h1.w;
            acc2 += w0 * h2.x; acc2 += w1 * h2.y; acc2 += w2 * h2.z; acc2 += w3 * h2.w;
            acc3 += w0 * h3.x; acc3 += w1 * h3.y; acc3 += w2 * h3.z; acc3 += w3 * h3.w;
        }
        z_s[tid][0] = acc0;
        z_s[tid][1] = acc1;
        z_s[tid][2] = acc2;
        z_s[tid][3] = acc3;
        __syncthreads();

        // phase 2: all 256 threads = 4 rows x 64 h-indices
        {
            float zi = z_s[jj][r2];
            float zf = z_s[64 + jj][r2];
            float zg = z_s[128 + jj][r2];
            float zo = z_s[192 + jj][r2];
            float ig = sigmoidf_(zi);
            float fg = sigmoidf_(zf);
            float og = sigmoidf_(zo);
            float gg = fmaxf(zg, 0.f);
            c = fg * c + ig * gg;
            float h = og * fmaxf(c, 0.f);
            float* own = &h_s[(p ^ 1) * 512 + r2 * 128 + jg];
            *own = h;
            st_remote_f32(own, peer, h);
            hseq[((size_t)(b0 + r2) * TT + t) * 128 + jg] = h;
        }
        cp_async_wait0();
        cluster_sync_();   // release own-half writes to peer; acquire peer half
        p ^= 1;
        gb ^= 1;
    }
}

// ---------------- host orchestration ----------------------------------------
extern "C" void kernel_launch(void* const* d_in, const int* in_sizes, int n_in,
                              void* d_out, int out_size) {
    const float* x    = (const float*)d_in[0];
    const float* Wk1  = (const float*)d_in[1];
    const float* Wr1  = (const float*)d_in[2];
    const float* b1   = (const float*)d_in[3];
    const float* Wk2  = (const float*)d_in[4];
    const float* Wr2  = (const float*)d_in[5];
    const float* b2   = (const float*)d_in[6];
    const float* Wd1k = (const float*)d_in[7];
    const float* Wd1r = (const float*)d_in[8];
    const float* bd1  = (const float*)d_in[9];
    const float* Wd2k = (const float*)d_in[10];
    const float* Wd2r = (const float*)d_in[11];
    const float* bd2  = (const float*)d_in[12];
    const float* Wout = (const float*)d_in[13];
    const float* bout = (const float*)d_in[14];
    float* out = (float*)d_out;

    float *bufG, *h1, *d1, *d2, *z, *gd1;
    cudaGetSymbolAddress((void**)&bufG, g_bufG);
    cudaGetSymbolAddress((void**)&h1,  g_h1);
    cudaGetSymbolAddress((void**)&d1,  g_d1);
    cudaGetSymbolAddress((void**)&d2,  g_d2);
    cudaGetSymbolAddress((void**)&z,   g_z);
    cudaGetSymbolAddress((void**)&gd1, g_gd1);

    const int SMEM128 = 148480;  // bytes
    const int SMEM64  = 72704;
    cudaFuncSetAttribute(lstm128_kernel, cudaFuncAttributeMaxDynamicSharedMemorySize, SMEM128);
    cudaFuncSetAttribute(lstm64_kernel,  cudaFuncAttributeMaxDynamicSharedMemorySize, SMEM64);

    dim3 blk(256);

    // 1) G1 = x @ Wk1 + b1                     [BT,512]
    gemm_bias_kernel<<<dim3(2048, 8), blk>>>(x, Wk1, b1, bufG, BT, 512, 64);
    // 2) encoder L1 recurrence -> h1           [BT,128]
    lstm128_kernel<<<128, blk, SMEM128>>>(bufG, Wr1, h1);
    // 3) G2 = h1 @ Wk2 + b2                    [BT,256]
    gemm_bias_kernel<<<dim3(2048, 4), blk>>>(h1, Wk2, b2, bufG, BT, 256, 128);
    // 4) encoder L2 recurrence -> z (last h)   [256,64]
    lstm64_kernel<<<128, blk, SMEM64>>>(bufG, Wr2, nullptr, z, 0);
    // 5) Gd1 = z @ Wd1k + bd1 (constant/step)  [256,256]
    gemm_bias_kernel<<<dim3(4, 4), blk>>>(z, Wd1k, bd1, gd1, 256, 256, 64);
    // 6) decoder L1 recurrence -> d1           [BT,64]
    lstm64_kernel<<<128, blk, SMEM64>>>(gd1, Wd1r, d1, nullptr, 1);
    // 7) Gd2 = d1 @ Wd2k + bd2                 [BT,512]
    gemm_bias_kernel<<<dim3(2048, 8), blk>>>(d1, Wd2k, bd2, bufG, BT, 512, 64);
    // 8) decoder L2 recurrence -> d2           [BT,128]
    lstm128_kernel<<<128, blk, SMEM128>>>(bufG, Wd2r, d2);
    // 9) out = d2 @ Wout + bout                [BT,64] == [B,T,F]
    gemm_bias_kernel<<<dim3(2048, 1), blk>>>(d2, Wout, bout, out, BT, 64, 128);
}

// round 2
// speedup vs baseline: 1.0755x; 1.0755x over previous
#include <cuda_runtime.h>
#include <cstdint>

#define BT 131072   // B*T = 256*512
#define TT 512

typedef unsigned long long ull;

// ---------------- scratch (device globals; no runtime allocation) ----------
__device__ float g_bufG[67108864];  // [BT,512]  G1 / G2 / Gd2 (reused)
__device__ float g_h1[16777216];    // [BT,128]
__device__ float g_d1[8388608];     // [BT,64]
__device__ float g_d2[16777216];    // [BT,128]
__device__ float g_z[16384];        // [256,64]
__device__ float g_gd1[65536];      // [256,256]

// ---------------- packed f32x2 helpers --------------------------------------
__device__ __forceinline__ ull dup2(float x) {
    ull r; asm("mov.b64 %0, {%1, %1};" : "=l"(r) : "f"(x)); return r;
}
__device__ __forceinline__ ull pack2(float lo, float hi) {
    ull r; asm("mov.b64 %0, {%1, %2};" : "=l"(r) : "f"(lo), "f"(hi)); return r;
}
__device__ __forceinline__ float2 unpack2(ull v) {
    float2 f; asm("mov.b64 {%0, %1}, %2;" : "=f"(f.x), "=f"(f.y) : "l"(v)); return f;
}
__device__ __forceinline__ void fma2(ull& acc, ull a, ull b) {
    asm("fma.rn.f32x2 %0, %1, %2, %0;" : "+l"(acc) : "l"(a), "l"(b));
}
__device__ __forceinline__ ull add2(ull a, ull b) {
    ull d; asm("add.rn.f32x2 %0, %1, %2;" : "=l"(d) : "l"(a), "l"(b)); return d;
}

// ---------------- misc helpers ----------------------------------------------
__device__ __forceinline__ void cp_async16(void* smem_dst, const void* gmem_src) {
    uint32_t s = (uint32_t)__cvta_generic_to_shared(smem_dst);
    asm volatile("cp.async.cg.shared.global [%0], [%1], 16;\n" :: "r"(s), "l"(gmem_src));
}
__device__ __forceinline__ void cp_async_commit() { asm volatile("cp.async.commit_group;\n"); }
__device__ __forceinline__ void cp_async_wait0()  { asm volatile("cp.async.wait_group 0;\n"); }

__device__ __forceinline__ void cluster_sync_() {
    asm volatile("barrier.cluster.arrive.aligned;\n" ::: "memory");
    asm volatile("barrier.cluster.wait.aligned;\n" ::: "memory");
}
__device__ __forceinline__ void st_remote_u64(void* local_ptr, uint32_t peer, ull v) {
    uint32_t la = (uint32_t)__cvta_generic_to_shared(local_ptr);
    uint32_t ra;
    asm("mapa.shared::cluster.u32 %0, %1, %2;\n" : "=r"(ra) : "r"(la), "r"(peer));
    asm volatile("st.shared::cluster.b64 [%0], %1;\n" :: "r"(ra), "l"(v) : "memory");
}
__device__ __forceinline__ void mbar_arrive_remote(uint32_t local_mbar, uint32_t peer) {
    uint32_t ra;
    asm("mapa.shared::cluster.u32 %0, %1, %2;\n" : "=r"(ra) : "r"(local_mbar), "r"(peer));
    asm volatile("mbarrier.arrive.release.cluster.shared::cluster.b64 _, [%0];\n"
                 :: "r"(ra) : "memory");
}
__device__ __forceinline__ void mbar_wait(uint32_t mbar, uint32_t parity) {
    asm volatile(
        "{\n\t.reg .pred P;\n"
        "WAITL_%=:\n\t"
        "mbarrier.try_wait.parity.acquire.cluster.shared::cta.b64 P, [%0], %1, 0x989680;\n\t"
        "@!P bra WAITL_%=;\n"
        "}" :: "r"(mbar), "r"(parity) : "memory");
}
__device__ __forceinline__ float sigmoidf_(float x) {
    return 1.0f / (1.0f + __expf(-x));
}

// ---------------- bulk GEMM: C[M,N] = A[M,K] @ W[K,N] + bias ----------------
// 128xBN tile, BK=16, 256 threads, f32x2 accumulation. M%128==0, N%BN==0, K%16==0.
template<int BN>
__global__ void __launch_bounds__(256)
gemm_f32x2_kernel(const float* __restrict__ A,
                  const float* __restrict__ W,
                  const float* __restrict__ bias,
                  float* __restrict__ C,
                  int M, int N, int K) {
    __shared__ __align__(16) float As[2][16][128];
    __shared__ __align__(16) float Bs[2][16][BN];
    const int tid = threadIdx.x;
    const int m0 = blockIdx.x * 128, n0 = blockIdx.y * BN;
    const int tx = tid & 15, ty = tid >> 4;
    const int NJ = (BN == 128) ? 4 : 2;   // u64 col-pairs per thread

    // A load mapping: 2 float4 per thread
    const int am = tid >> 1, ak = (tid & 1) * 8;
    // B load mapping (cp.async)
    const int NB_F4 = 16 * BN / 4;                       // float4s per B tile
    const int nper = NB_F4 / 256;                        // 2 (BN=128) or 1 (BN=64)

    ull acc[8][4];
#pragma unroll
    for (int i = 0; i < 8; i++)
#pragma unroll
        for (int j = 0; j < 4; j++) acc[i][j] = 0ull;

    const int nk = K / 16;

    // prologue: tile 0
    {
        const float* ap = A + (size_t)(m0 + am) * K + ak;
        float4 va = *(const float4*)ap;
        float4 vb = *(const float4*)(ap + 4);
#pragma unroll
        for (int q = 0; q < nper; q++) {
            int idx = tid * nper + q;
            int br = idx / (BN / 4), bc = (idx % (BN / 4)) * 4;
            cp_async16(&Bs[0][br][bc], W + (size_t)br * N + n0 + bc);
        }
        cp_async_commit();
        As[0][ak + 0][am] = va.x; As[0][ak + 1][am] = va.y;
        As[0][ak + 2][am] = va.z; As[0][ak + 3][am] = va.w;
        As[0][ak + 4][am] = vb.x; As[0][ak + 5][am] = vb.y;
        As[0][ak + 6][am] = vb.z; As[0][ak + 7][am] = vb.w;
        cp_async_wait0();
        __syncthreads();
    }

    for (int kt = 0; kt < nk; kt++) {
        const int p = kt & 1;
        const bool more = (kt + 1) < nk;
        float4 va, vb;
        if (more) {
            const float* ap = A + (size_t)(m0 + am) * K + (kt + 1) * 16 + ak;
            va = *(const float4*)ap;
            vb = *(const float4*)(ap + 4);
#pragma unroll
            for (int q = 0; q < nper; q++) {
                int idx = tid * nper + q;
                int br = idx / (BN / 4), bc = (idx % (BN / 4)) * 4;
                cp_async16(&Bs[p ^ 1][br][bc], W + (size_t)((kt + 1) * 16 + br) * N + n0 + bc);
            }
        }
        cp_async_commit();

#pragma unroll
        for (int k = 0; k < 16; k++) {
            float4 a0 = *(const float4*)&As[p][k][ty * 4];
            float4 a1 = *(const float4*)&As[p][k][64 + ty * 4];
            ulonglong2 b0 = *(const ulonglong2*)&Bs[p][k][tx * 4];
            ulonglong2 b1;
            if (BN == 128) b1 = *(const ulonglong2*)&Bs[p][k][64 + tx * 4];
            float av[8] = {a0.x, a0.y, a0.z, a0.w, a1.x, a1.y, a1.z, a1.w};
#pragma unroll
            for (int i = 0; i < 8; i++) {
                ull aa = dup2(av[i]);
                fma2(acc[i][0], aa, b0.x);
                fma2(acc[i][1], aa, b0.y);
                if (BN == 128) {
                    fma2(acc[i][2], aa, b1.x);
                    fma2(acc[i][3], aa, b1.y);
                }
            }
        }

        if (more) {
            As[p ^ 1][ak + 0][am] = va.x; As[p ^ 1][ak + 1][am] = va.y;
            As[p ^ 1][ak + 2][am] = va.z; As[p ^ 1][ak + 3][am] = va.w;
            As[p ^ 1][ak + 4][am] = vb.x; As[p ^ 1][ak + 5][am] = vb.y;
            As[p ^ 1][ak + 6][am] = vb.z; As[p ^ 1][ak + 7][am] = vb.w;
        }
        cp_async_wait0();
        __syncthreads();
    }

    // epilogue: bias + store
    ull bz[4];
    bz[0] = *(const ull*)&bias[n0 + tx * 4];
    bz[1] = *(const ull*)&bias[n0 + tx * 4 + 2];
    if (BN == 128) {
        bz[2] = *(const ull*)&bias[n0 + 64 + tx * 4];
        bz[3] = *(const ull*)&bias[n0 + 64 + tx * 4 + 2];
    }
#pragma unroll
    for (int i = 0; i < 8; i++) {
        int row = m0 + ((i < 4) ? (ty * 4 + i) : (64 + ty * 4 + i - 4));
        ulonglong2 o0;
        o0.x = add2(acc[i][0], bz[0]);
        o0.y = add2(acc[i][1], bz[1]);
        *(ulonglong2*)&C[(size_t)row * N + n0 + tx * 4] = o0;
        if (BN == 128) {
            ulonglong2 o1;
            o1.x = add2(acc[i][2], bz[2]);
            o1.y = add2(acc[i][3], bz[3]);
            *(ulonglong2*)&C[(size_t)row * N + n0 + 64 + tx * 4] = o1;
        }
    }
}

// ---------------- LSTM recurrence, H=64 (encoder L2 / decoder L1) -----------
// 128 CTAs x 256 threads, each CTA owns 2 batch rows (packed as f32x2 lanes).
// Weight column pre-duplicated into 64 u64 registers per thread.
__global__ void __launch_bounds__(256, 1)
lstm64_kernel(const float* __restrict__ gproj, // [BT,256] or [256,256] if constProj
              const float* __restrict__ Wr,    // [64,256]
              float* __restrict__ hseq,        // [BT,64] or null
              float* __restrict__ hlast,       // [256,64] or null
              int constProj) {
    __shared__ __align__(16) ull h2u[2][64];   // (h_row0, h_row1) pairs
    __shared__ __align__(16) ull z2u[256];
    __shared__ __align__(16) float gbuf[2][2][256];

    const int tid = threadIdx.x;
    const int b0 = blockIdx.x * 2;

    // weights -> registers, duplicated
    ull w2[64];
#pragma unroll
    for (int k = 0; k < 64; k++) w2[k] = dup2(Wr[k * 256 + tid]);

    if (tid < 64) h2u[0][tid] = 0ull;

    ull g2c = 0ull;
    if (constProj) {
        g2c = pack2(gproj[(size_t)b0 * 256 + tid], gproj[(size_t)(b0 + 1) * 256 + tid]);
    } else {
        if (tid < 128) {
            int r = tid >> 6, c4 = (tid & 63) * 4;
            cp_async16(&gbuf[0][r][c4], gproj + ((size_t)(b0 + r) * TT) * 256 + c4);
        }
        cp_async_commit();
        cp_async_wait0();
    }
    __syncthreads();

    float2 cc = make_float2(0.f, 0.f);
    int p = 0, gb = 0;

    for (int t = 0; t < TT; t++) {
        if (!constProj && (t + 1) < TT && tid < 128) {
            int r = tid >> 6, c4 = (tid & 63) * 4;
            cp_async16(&gbuf[gb ^ 1][r][c4],
                       gproj + ((size_t)(b0 + r) * TT + (t + 1)) * 256 + c4);
        }
        cp_async_commit();

        // phase 1: z(col tid) over both rows, packed
        ull a0 = constProj ? g2c : pack2(gbuf[gb][0][tid], gbuf[gb][1][tid]);
        ull a1 = 0ull;
        const ull* hp = h2u[p];
#pragma unroll
        for (int k = 0; k < 64; k += 4) {
            ulonglong2 hA = *(const ulonglong2*)&hp[k];
            ulonglong2 hB = *(const ulonglong2*)&hp[k + 2];
            fma2(a0, w2[k + 0], hA.x);
            fma2(a1, w2[k + 1], hA.y);
            fma2(a0, w2[k + 2], hB.x);
            fma2(a1, w2[k + 3], hB.y);
        }
        z2u[tid] = add2(a0, a1);
        __syncthreads();

        // phase 2: threads 0..63 own h-index tid for both rows
        if (tid < 64) {
            float2 zi = unpack2(z2u[tid]);
            float2 zf = unpack2(z2u[64 + tid]);
            float2 zg = unpack2(z2u[128 + tid]);
            float2 zo = unpack2(z2u[192 + tid]);
            cc.x = sigmoidf_(zf.x) * cc.x + sigmoidf_(zi.x) * fmaxf(zg.x, 0.f);
            cc.y = sigmoidf_(zf.y) * cc.y + sigmoidf_(zi.y) * fmaxf(zg.y, 0.f);
            float h0 = sigmoidf_(zo.x) * fmaxf(cc.x, 0.f);
            float h1 = sigmoidf_(zo.y) * fmaxf(cc.y, 0.f);
            h2u[p ^ 1][tid] = pack2(h0, h1);
            if (hseq) {
                hseq[((size_t)b0 * TT + t) * 64 + tid] = h0;
                hseq[((size_t)(b0 + 1) * TT + t) * 64 + tid] = h1;
            }
        }
        cp_async_wait0();
        __syncthreads();
        p ^= 1;
        gb ^= 1;
    }
    if (hlast && tid < 64) {
        float2 h = unpack2(h2u[p][tid]);
        hlast[(size_t)b0 * 64 + tid] = h.x;
        hlast[(size_t)(b0 + 1) * 64 + tid] = h.y;
    }
}

// ---------------- LSTM recurrence, H=128 (encoder L1 / decoder L2) ----------
// 2-CTA cluster, 64 clusters = 128 CTAs, 4 batch rows per CTA (2 row-pairs).
// Each CTA holds 256 of the 512 gate columns (its 64 h-indices x 4 gates).
// Per step: computes its half of h(t) as f32x2 pairs, pushes to peer SMEM,
// signals peer's mbarrier with per-thread release-arrive (count=128).
// dyn smem (floats): Wr_s 32768 | z2u 1024 | h2u 1024 | gbuf 2048 | mbar 2
__global__ void __launch_bounds__(256, 1) __cluster_dims__(2, 1, 1)
lstm128_kernel(const float* __restrict__ gproj, // [BT,512]
               const float* __restrict__ Wr,    // [128,512]
               float* __restrict__ hseq) {      // [BT,128]
    extern __shared__ float sm[];
    float* Wr_s = sm;                              // [128][256]
    ull* z2u = (ull*)(sm + 32768);                 // [2 rp][256 col]
    ull* h2u = (ull*)(sm + 32768 + 1024);          // [2 buf][2 rp][128]
    float* gbuf = sm + 32768 + 2048;               // [2 buf][4 r][256]
    uint32_t mbar = (uint32_t)__cvta_generic_to_shared(sm + 32768 + 2048 + 2048);

    const int tid = threadIdx.x;
    uint32_t q;
    asm("mov.u32 %0, %%cluster_ctarank;" : "=r"(q));
    const uint32_t peer = q ^ 1u;
    const int b0 = (blockIdx.x >> 1) * 4;

    // load Wr slice: local col n -> global col (n>>6)*128 + q*64 + (n&63)
    for (int i = tid; i < 128 * 256; i += 256) {
        int k = i >> 8, n = i & 255;
        Wr_s[i] = Wr[(size_t)k * 512 + ((n >> 6) * 128 + (int)q * 64 + (n & 63))];
    }
    for (int i = tid; i < 256; i += 256) h2u[i] = 0ull;   // buf 0
    if (tid == 0)
        asm volatile("mbarrier.init.shared.b64 [%0], %1;\n" :: "r"(mbar), "r"(128u) : "memory");
    __syncthreads();

    // gbuf prefetch mapping
    const int pr = tid >> 6, pt4 = (tid & 63) * 4;
    const int pcol = (pt4 >> 6) * 128 + (int)q * 64 + (pt4 & 63);
    cp_async16(&gbuf[pr * 256 + pt4], gproj + ((size_t)(b0 + pr) * TT) * 512 + pcol);
    cp_async_commit();
    cp_async_wait0();
    __syncthreads();
    cluster_sync_();   // mbars + h buffers + weights visible cluster-wide

    const int rp2 = tid >> 6;           // phase-2 row-pair (tid<128)
    const int jj = tid & 63;
    const int jg = (int)q * 64 + jj;
    float2 cc = make_float2(0.f, 0.f);

    int p = 0, gb = 0;
    uint32_t par = 0;
    for (int t = 0; t < TT; t++) {
        if ((t + 1) < TT)
            cp_async16(&gbuf[(gb ^ 1) * 1024 + pr * 256 + pt4],
                       gproj + ((size_t)(b0 + pr) * TT + (t + 1)) * 512 + pcol);
        cp_async_commit();

        // phase 1: z for local col tid, two row-pairs
        ull acc0 = pack2(gbuf[gb * 1024 + tid], gbuf[gb * 1024 + 256 + tid]);
        ull acc1 = pack2(gbuf[gb * 1024 + 512 + tid], gbuf[gb * 1024 + 768 + tid]);
        ull b0a = 0ull, b1a = 0ull;
        const ull* hpA = h2u + p * 256;         // rp0
        const ull* hpB = h2u + p * 256 + 128;   // rp1
#pragma unroll 8
        for (int k = 0; k < 128; k += 2) {
            ulonglong2 hA = *(const ulonglong2*)&hpA[k];
            ulonglong2 hB = *(const ulonglong2*)&hpB[k];
            ull wd0 = dup2(Wr_s[k * 256 + tid]);
            ull wd1 = dup2(Wr_s[(k + 1) * 256 + tid]);
            fma2(acc0, wd0, hA.x);
            fma2(b0a, wd1, hA.y);
            fma2(acc1, wd0, hB.x);
            fma2(b1a, wd1, hB.y);
        }
        z2u[tid] = add2(acc0, b0a);
        z2u[256 + tid] = add2(acc1, b1a);
        __syncthreads();

        // phase 2: 128 threads = 2 row-pairs x 64 local h-indices
        if (tid < 128) {
            const ull* zz = z2u + rp2 * 256;
            float2 zi = unpack2(zz[jj]);
            float2 zf = unpack2(zz[64 + jj]);
            float2 zg = unpack2(zz[128 + jj]);
            float2 zo = unpack2(zz[192 + jj]);
            cc.x = sigmoidf_(zf.x) * cc.x + sigmoidf_(zi.x) * fmaxf(zg.x, 0.f);
            cc.y = sigmoidf_(zf.y) * cc.y + sigmoidf_(zi.y) * fmaxf(zg.y, 0.f);
            float h0 = sigmoidf_(zo.x) * fmaxf(cc.x, 0.f);
            float h1 = sigmoidf_(zo.y) * fmaxf(cc.y, 0.f);
            ull hv = pack2(h0, h1);
            ull* own = &h2u[(p ^ 1) * 256 + rp2 * 128 + jg];
            *own = hv;
            st_remote_u64(own, peer, hv);
            hseq[((size_t)(b0 + 2 * rp2) * TT + t) * 128 + jg] = h0;
            hseq[((size_t)(b0 + 2 * rp2 + 1) * TT + t) * 128 + jg] = h1;
            mbar_arrive_remote(mbar, peer);   // release: orders remote h stores
        }
        cp_async_wait0();
        __syncthreads();                      // local half + z2u reuse ordering
        mbar_wait(mbar, par);                 // acquire peer's 128 arrivals
        par ^= 1;
        p ^= 1;
        gb ^= 1;
    }
}

// ---------------- host orchestration ----------------------------------------
extern "C" void kernel_launch(void* const* d_in, const int* in_sizes, int n_in,
                              void* d_out, int out_size) {
    const float* x    = (const float*)d_in[0];
    const float* Wk1  = (const float*)d_in[1];
    const float* Wr1  = (const float*)d_in[2];
    const float* b1   = (const float*)d_in[3];
    const float* Wk2  = (const float*)d_in[4];
    const float* Wr2  = (const float*)d_in[5];
    const float* b2   = (const float*)d_in[6];
    const float* Wd1k = (const float*)d_in[7];
    const float* Wd1r = (const float*)d_in[8];
    const float* bd1  = (const float*)d_in[9];
    const float* Wd2k = (const float*)d_in[10];
    const float* Wd2r = (const float*)d_in[11];
    const float* bd2  = (const float*)d_in[12];
    const float* Wout = (const float*)d_in[13];
    const float* bout = (const float*)d_in[14];
    float* out = (float*)d_out;

    float *bufG, *h1, *d1, *d2, *z, *gd1;
    cudaGetSymbolAddress((void**)&bufG, g_bufG);
    cudaGetSymbolAddress((void**)&h1,  g_h1);
    cudaGetSymbolAddress((void**)&d1,  g_d1);
    cudaGetSymbolAddress((void**)&d2,  g_d2);
    cudaGetSymbolAddress((void**)&z,   g_z);
    cudaGetSymbolAddress((void**)&gd1, g_gd1);

    const int SMEM128 = 147584;  // bytes of dynamic smem for lstm128
    cudaFuncSetAttribute(lstm128_kernel, cudaFuncAttributeMaxDynamicSharedMemorySize, SMEM128);

    dim3 blk(256);

    // 1) G1 = x @ Wk1 + b1                     [BT,512]
    gemm_f32x2_kernel<128><<<dim3(1024, 4), blk>>>(x, Wk1, b1, bufG, BT, 512, 64);
    // 2) encoder L1 recurrence -> h1           [BT,128]
    lstm128_kernel<<<128, blk, SMEM128>>>(bufG, Wr1, h1);
    // 3) G2 = h1 @ Wk2 + b2                    [BT,256]
    gemm_f32x2_kernel<128><<<dim3(1024, 2), blk>>>(h1, Wk2, b2, bufG, BT, 256, 128);
    // 4) encoder L2 recurrence -> z (last h)   [256,64]
    lstm64_kernel<<<128, blk>>>(bufG, Wr2, nullptr, z, 0);
    // 5) Gd1 = z @ Wd1k + bd1 (constant/step)  [256,256]
    gemm_f32x2_kernel<128><<<dim3(2, 2), blk>>>(z, Wd1k, bd1, gd1, 256, 256, 64);
    // 6) decoder L1 recurrence -> d1           [BT,64]
    lstm64_kernel<<<128, blk>>>(gd1, Wd1r, d1, nullptr, 1);
    // 7) Gd2 = d1 @ Wd2k + bd2                 [BT,512]
    gemm_f32x2_kernel<128><<<dim3(1024, 4), blk>>>(d1, Wd2k, bd2, bufG, BT, 512, 64);
    // 8) decoder L2 recurrence -> d2           [BT,128]
    lstm128_kernel<<<128, blk, SMEM128>>>(bufG, Wd2r, d2);
    // 9) out = d2 @ Wout + bout                [BT,64] == [B,T,F]
    gemm_f32x2_kernel<64><<<dim3(1024, 1), blk>>>(d2, Wout, bout, out, BT, 64, 128);
}

// round 3
// speedup vs baseline: 1.4446x; 1.3432x over previous
#include <cuda_runtime.h>
#include <cstdint>

#define BT 131072   // B*T = 256*512
#define TT 512

typedef unsigned long long ull;

// ---------------- scratch (device globals; no runtime allocation) ----------
__device__ float g_bufG[67108864];  // [BT,512]  G1 / G2 / Gd2 (reused)
__device__ float g_h1[16777216];    // [BT,128]
__device__ float g_d1[8388608];     // [BT,64]
__device__ float g_d2[16777216];    // [BT,128]
__device__ float g_z[16384];        // [256,64]
__device__ float g_gd1[65536];      // [256,256]

// ---------------- packed f32x2 helpers --------------------------------------
__device__ __forceinline__ ull dup2(float x) {
    ull r; asm("mov.b64 %0, {%1, %1};" : "=l"(r) : "f"(x)); return r;
}
__device__ __forceinline__ ull pack2(float lo, float hi) {
    ull r; asm("mov.b64 %0, {%1, %2};" : "=l"(r) : "f"(lo), "f"(hi)); return r;
}
__device__ __forceinline__ float2 unpack2(ull v) {
    float2 f; asm("mov.b64 {%0, %1}, %2;" : "=f"(f.x), "=f"(f.y) : "l"(v)); return f;
}
__device__ __forceinline__ void fma2(ull& acc, ull a, ull b) {
    asm("fma.rn.f32x2 %0, %1, %2, %0;" : "+l"(acc) : "l"(a), "l"(b));
}
__device__ __forceinline__ ull add2(ull a, ull b) {
    ull d; asm("add.rn.f32x2 %0, %1, %2;" : "=l"(d) : "l"(a), "l"(b)); return d;
}

// fast sigmoid: 1/(1 + 2^(-x*log2e)) via ex2.approx + rcp.approx (~1e-6 rel)
__device__ __forceinline__ float fsig(float x) {
    float r;
    asm("{\n\t.reg .f32 t;\n\t"
        "mul.f32 t, %1, 0fBFB8AA3B;\n\t"
        "ex2.approx.f32 t, t;\n\t"
        "add.f32 t, t, 0f3F800000;\n\t"
        "rcp.approx.f32 %0, t;\n\t}"
        : "=f"(r) : "f"(x));
    return r;
}

// ---------------- misc helpers ----------------------------------------------
__device__ __forceinline__ void cp_async16(void* smem_dst, const void* gmem_src) {
    uint32_t s = (uint32_t)__cvta_generic_to_shared(smem_dst);
    asm volatile("cp.async.cg.shared.global [%0], [%1], 16;\n" :: "r"(s), "l"(gmem_src));
}
__device__ __forceinline__ void cp_async_commit() { asm volatile("cp.async.commit_group;\n"); }
__device__ __forceinline__ void cp_async_wait6()  { asm volatile("cp.async.wait_group 6;\n"); }

__device__ __forceinline__ void cluster_sync_() {
    asm volatile("barrier.cluster.arrive.aligned;\n" ::: "memory");
    asm volatile("barrier.cluster.wait.aligned;\n" ::: "memory");
}
__device__ __forceinline__ void st_remote_f32(float* local_ptr, uint32_t peer, float v) {
    uint32_t la = (uint32_t)__cvta_generic_to_shared(local_ptr);
    uint32_t ra;
    asm("mapa.shared::cluster.u32 %0, %1, %2;\n" : "=r"(ra) : "r"(la), "r"(peer));
    asm volatile("st.shared::cluster.f32 [%0], %1;\n" :: "r"(ra), "f"(v) : "memory");
}
__device__ __forceinline__ void mbar_arrive_remote(uint32_t local_mbar, uint32_t peer) {
    uint32_t ra;
    asm("mapa.shared::cluster.u32 %0, %1, %2;\n" : "=r"(ra) : "r"(local_mbar), "r"(peer));
    asm volatile("mbarrier.arrive.release.cluster.shared::cluster.b64 _, [%0];\n"
                 :: "r"(ra) : "memory");
}
__device__ __forceinline__ void mbar_wait(uint32_t mbar, uint32_t parity) {
    asm volatile(
        "{\n\t.reg .pred P;\n"
        "WAITL_%=:\n\t"
        "mbarrier.try_wait.parity.acquire.cluster.shared::cta.b64 P, [%0], %1, 0x989680;\n\t"
        "@!P bra WAITL_%=;\n"
        "}" :: "r"(mbar), "r"(parity) : "memory");
}

// ---------------- bulk GEMM: C[M,N] = A[M,K] @ W[K,N] + bias ----------------
// 128xBN tile, BK=16, 256 threads, f32x2 accumulation. M%128==0, N%BN==0, K%16==0.
template<int BN>
__global__ void __launch_bounds__(256)
gemm_f32x2_kernel(const float* __restrict__ A,
                  const float* __restrict__ W,
                  const float* __restrict__ bias,
                  float* __restrict__ C,
                  int M, int N, int K) {
    __shared__ __align__(16) float As[2][16][128];
    __shared__ __align__(16) float Bs[2][16][BN];
    const int tid = threadIdx.x;
    const int m0 = blockIdx.x * 128, n0 = blockIdx.y * BN;
    const int tx = tid & 15, ty = tid >> 4;

    const int am = tid >> 1, ak = (tid & 1) * 8;
    const int NB_F4 = 16 * BN / 4;
    const int nper = NB_F4 / 256;

    ull acc[8][4];
#pragma unroll
    for (int i = 0; i < 8; i++)
#pragma unroll
        for (int j = 0; j < 4; j++) acc[i][j] = 0ull;

    const int nk = K / 16;

    {
        const float* ap = A + (size_t)(m0 + am) * K + ak;
        float4 va = *(const float4*)ap;
        float4 vb = *(const float4*)(ap + 4);
#pragma unroll
        for (int q = 0; q < nper; q++) {
            int idx = tid * nper + q;
            int br = idx / (BN / 4), bc = (idx % (BN / 4)) * 4;
            cp_async16(&Bs[0][br][bc], W + (size_t)br * N + n0 + bc);
        }
        cp_async_commit();
        As[0][ak + 0][am] = va.x; As[0][ak + 1][am] = va.y;
        As[0][ak + 2][am] = va.z; As[0][ak + 3][am] = va.w;
        As[0][ak + 4][am] = vb.x; As[0][ak + 5][am] = vb.y;
        As[0][ak + 6][am] = vb.z; As[0][ak + 7][am] = vb.w;
        asm volatile("cp.async.wait_group 0;\n");
        __syncthreads();
    }

    for (int kt = 0; kt < nk; kt++) {
        const int p = kt & 1;
        const bool more = (kt + 1) < nk;
        float4 va, vb;
        if (more) {
            const float* ap = A + (size_t)(m0 + am) * K + (kt + 1) * 16 + ak;
            va = *(const float4*)ap;
            vb = *(const float4*)(ap + 4);
#pragma unroll
            for (int q = 0; q < nper; q++) {
                int idx = tid * nper + q;
                int br = idx / (BN / 4), bc = (idx % (BN / 4)) * 4;
                cp_async16(&Bs[p ^ 1][br][bc], W + (size_t)((kt + 1) * 16 + br) * N + n0 + bc);
            }
        }
        cp_async_commit();

#pragma unroll
        for (int k = 0; k < 16; k++) {
            float4 a0 = *(const float4*)&As[p][k][ty * 4];
            float4 a1 = *(const float4*)&As[p][k][64 + ty * 4];
            ulonglong2 b0v = *(const ulonglong2*)&Bs[p][k][tx * 4];
            ulonglong2 b1v;
            if (BN == 128) b1v = *(const ulonglong2*)&Bs[p][k][64 + tx * 4];
            float av[8] = {a0.x, a0.y, a0.z, a0.w, a1.x, a1.y, a1.z, a1.w};
#pragma unroll
            for (int i = 0; i < 8; i++) {
                ull aa = dup2(av[i]);
                fma2(acc[i][0], aa, b0v.x);
                fma2(acc[i][1], aa, b0v.y);
                if (BN == 128) {
                    fma2(acc[i][2], aa, b1v.x);
                    fma2(acc[i][3], aa, b1v.y);
                }
            }
        }

        if (more) {
            As[p ^ 1][ak + 0][am] = va.x; As[p ^ 1][ak + 1][am] = va.y;
            As[p ^ 1][ak + 2][am] = va.z; As[p ^ 1][ak + 3][am] = va.w;
            As[p ^ 1][ak + 4][am] = vb.x; As[p ^ 1][ak + 5][am] = vb.y;
            As[p ^ 1][ak + 6][am] = vb.z; As[p ^ 1][ak + 7][am] = vb.w;
        }
        asm volatile("cp.async.wait_group 0;\n");
        __syncthreads();
    }

    ull bz[4];
    bz[0] = *(const ull*)&bias[n0 + tx * 4];
    bz[1] = *(const ull*)&bias[n0 + tx * 4 + 2];
    if (BN == 128) {
        bz[2] = *(const ull*)&bias[n0 + 64 + tx * 4];
        bz[3] = *(const ull*)&bias[n0 + 64 + tx * 4 + 2];
    }
#pragma unroll
    for (int i = 0; i < 8; i++) {
        int row = m0 + ((i < 4) ? (ty * 4 + i) : (64 + ty * 4 + i - 4));
        ulonglong2 o0;
        o0.x = add2(acc[i][0], bz[0]);
        o0.y = add2(acc[i][1], bz[1]);
        *(ulonglong2*)&C[(size_t)row * N + n0 + tx * 4] = o0;
        if (BN == 128) {
            ulonglong2 o1;
            o1.x = add2(acc[i][2], bz[2]);
            o1.y = add2(acc[i][3], bz[3]);
            *(ulonglong2*)&C[(size_t)row * N + n0 + 64 + tx * 4] = o1;
        }
    }
}

// ---------------- LSTM recurrence, H=64 (encoder L2 / decoder L1) -----------
// 128 CTAs x 256 threads, 2 batch rows per CTA. Weights in registers as
// (w_k, w_{k+1}) u64 pairs; fma2 lanes hold even/odd-k partial sums
// (one horizontal add per step). 8-stage cp.async pipeline for gproj.
__global__ void __launch_bounds__(256)
lstm64_kernel(const float* __restrict__ gproj, // [BT,256] or [256,256] if constProj
              const float* __restrict__ Wr,    // [64,256]
              float* __restrict__ hseq,        // [BT,64] or null
              float* __restrict__ hlast,       // [256,64] or null
              int constProj) {
    __shared__ __align__(16) float h_s[2][2][64];
    __shared__ __align__(16) float z_s[2][256];
    __shared__ __align__(16) float gbuf[8][2][256];   // 16KB

    const int tid = threadIdx.x;
    const int b0 = blockIdx.x * 2;

    // weights -> registers, k-paired (32 u64)
    ull w2[32];
#pragma unroll
    for (int kp = 0; kp < 32; kp++)
        w2[kp] = pack2(Wr[(2 * kp) * 256 + tid], Wr[(2 * kp + 1) * 256 + tid]);

    if (tid < 128) h_s[0][tid >> 6][tid & 63] = 0.f;

    const int pr = tid >> 6, c4 = (tid & 63) * 4;   // prefetch mapping (tid<128)
    float g0c = 0.f, g1c = 0.f;
    if (constProj) {
        g0c = gproj[(size_t)b0 * 256 + tid];
        g1c = gproj[(size_t)(b0 + 1) * 256 + tid];
    } else {
        // prologue: stages 0..6 (7 groups in flight)
        for (int s = 0; s < 7; s++) {
            if (tid < 128)
                cp_async16(&gbuf[s][pr][c4], gproj + ((size_t)(b0 + pr) * TT + s) * 256 + c4);
            cp_async_commit();
        }
        cp_async_wait6();
    }
    __syncthreads();

    float c = 0.f;                 // cell state for (row tid>>6, idx tid&63), tid<128
    const int r2 = (tid >> 6) & 1, j2 = tid & 63;
    int p = 0;

    for (int t = 0; t < TT; t++) {
        const int st = t & 7;
        if (!constProj) {
            if (tid < 128 && t + 7 < TT)
                cp_async16(&gbuf[(t + 7) & 7][pr][c4],
                           gproj + ((size_t)(b0 + pr) * TT + t + 7) * 256 + c4);
            cp_async_commit();
        }

        // phase 1: z(col tid) for both rows; even/odd-k partials in fma2 lanes
        float gv0 = constProj ? g0c : gbuf[st][0][tid];
        float gv1 = constProj ? g1c : gbuf[st][1][tid];
        ull a0 = 0ull, a1 = 0ull, e0 = 0ull, e1 = 0ull;
        const float* h0p = h_s[p][0];
        const float* h1p = h_s[p][1];
#pragma unroll
        for (int kp = 0; kp < 32; kp += 2) {
            ulonglong2 u0 = *(const ulonglong2*)(h0p + 2 * kp);
            ulonglong2 u1 = *(const ulonglong2*)(h1p + 2 * kp);
            fma2(a0, w2[kp], u0.x);
            fma2(e0, w2[kp + 1], u0.y);
            fma2(a1, w2[kp], u1.x);
            fma2(e1, w2[kp + 1], u1.y);
        }
        float2 fa0 = unpack2(add2(a0, e0));
        float2 fa1 = unpack2(add2(a1, e1));
        z_s[0][tid] = gv0 + (fa0.x + fa0.y);
        z_s[1][tid] = gv1 + (fa1.x + fa1.y);
        __syncthreads();

        // phase 2: threads 0..127 = 2 rows x 64 h-indices
        if (tid < 128) {
            float zi = z_s[r2][j2];
            float zf = z_s[r2][64 + j2];
            float zg = z_s[r2][128 + j2];
            float zo = z_s[r2][192 + j2];
            c = fsig(zf) * c + fsig(zi) * fmaxf(zg, 0.f);
            float h = fsig(zo) * fmaxf(c, 0.f);
            h_s[p ^ 1][r2][j2] = h;
            if (hseq) hseq[((size_t)(b0 + r2) * TT + t) * 64 + j2] = h;
        }
        if (!constProj) cp_async_wait6();
        __syncthreads();
        p ^= 1;
    }
    if (hlast && tid < 128)
        hlast[(size_t)(b0 + r2) * 64 + j2] = h_s[p][r2][j2];
}

// ---------------- LSTM recurrence, H=128 (encoder L1 / decoder L2) ----------
// 2-CTA cluster, 64 clusters, 4 batch rows per CTA. Each CTA owns 256 of the
// 512 gate columns; weights in registers as k-pairs (64 u64). Per step it
// computes its half of h(t), pushes to peer SMEM via DSMEM, signals the peer
// with one release-arrive per warp (mbar count=8).
__global__ void __launch_bounds__(256) __cluster_dims__(2, 1, 1)
lstm128_kernel(const float* __restrict__ gproj, // [BT,512]
               const float* __restrict__ Wr,    // [128,512]
               float* __restrict__ hseq) {      // [BT,128]
    __shared__ __align__(16) float h_s[2][4][128];    // 4KB
    __shared__ __align__(16) float z_s[4][256];       // 4KB
    __shared__ __align__(16) float gbuf[8][4][256];   // 32KB
    __shared__ __align__(8) ull mbar_s;

    const int tid = threadIdx.x;
    uint32_t q;
    asm("mov.u32 %0, %%cluster_ctarank;" : "=r"(q));
    const uint32_t peer = q ^ 1u;
    const int b0 = (blockIdx.x >> 1) * 4;
    const int gcol = (tid >> 6) * 128 + (int)q * 64 + (tid & 63);

    // weights -> registers, k-paired (64 u64 = 128 regs)
    ull w2[64];
#pragma unroll
    for (int kp = 0; kp < 64; kp++)
        w2[kp] = pack2(Wr[(size_t)(2 * kp) * 512 + gcol],
                       Wr[(size_t)(2 * kp + 1) * 512 + gcol]);

    for (int i = tid; i < 512; i += 256) h_s[0][i >> 7][i & 127] = 0.f;
    const uint32_t mbar = (uint32_t)__cvta_generic_to_shared(&mbar_s);
    if (tid == 0)
        asm volatile("mbarrier.init.shared.b64 [%0], %1;\n" :: "r"(mbar), "r"(8u) : "memory");
    __syncthreads();

    // prefetch mapping: 1 float4 per thread per stage
    const int pr = tid >> 6, c4 = (tid & 63) * 4;
    const int pcol = (c4 >> 6) * 128 + (int)q * 64 + (c4 & 63);
    for (int s = 0; s < 7; s++) {
        cp_async16(&gbuf[s][pr][c4], gproj + ((size_t)(b0 + pr) * TT + s) * 512 + pcol);
        cp_async_commit();
    }
    cp_async_wait6();
    __syncthreads();
    cluster_sync_();   // mbar + h buffers visible cluster-wide

    const int r2 = tid >> 6, jj = tid & 63;
    const int jg = (int)q * 64 + jj;
    const int lane = tid & 31;
    float c = 0.f;
    int p = 0;
    uint32_t par = 0;

    for (int t = 0; t < TT; t++) {
        const int st = t & 7;
        if (t + 7 < TT)
            cp_async16(&gbuf[(t + 7) & 7][pr][c4],
                       gproj + ((size_t)(b0 + pr) * TT + t + 7) * 512 + pcol);
        cp_async_commit();

        // phase 1: col tid, 4 rows; even/odd-k partials in fma2 lanes
        ull a[4], e[4];
#pragma unroll
        for (int r = 0; r < 4; r++) { a[r] = 0ull; e[r] = 0ull; }
        const float* h0p = h_s[p][0];
        const float* h1p = h_s[p][1];
        const float* h2p = h_s[p][2];
        const float* h3p = h_s[p][3];
#pragma unroll
        for (int kp = 0; kp < 64; kp += 2) {
            ulonglong2 u0 = *(const ulonglong2*)(h0p + 2 * kp);
            ulonglong2 u1 = *(const ulonglong2*)(h1p + 2 * kp);
            ulonglong2 u2 = *(const ulonglong2*)(h2p + 2 * kp);
            ulonglong2 u3 = *(const ulonglong2*)(h3p + 2 * kp);
            fma2(a[0], w2[kp], u0.x); fma2(e[0], w2[kp + 1], u0.y);
            fma2(a[1], w2[kp], u1.x); fma2(e[1], w2[kp + 1], u1.y);
            fma2(a[2], w2[kp], u2.x); fma2(e[2], w2[kp + 1], u2.y);
            fma2(a[3], w2[kp], u3.x); fma2(e[3], w2[kp + 1], u3.y);
        }
#pragma unroll
        for (int r = 0; r < 4; r++) {
            float2 f = unpack2(add2(a[r], e[r]));
            z_s[r][tid] = gbuf[st][r][tid] + (f.x + f.y);
        }
        __syncthreads();

        // phase 2: 256 threads = 4 rows x 64 local h-indices
        {
            float zi = z_s[r2][jj];
            float zf = z_s[r2][64 + jj];
            float zg = z_s[r2][128 + jj];
            float zo = z_s[r2][192 + jj];
            c = fsig(zf) * c + fsig(zi) * fmaxf(zg, 0.f);
            float h = fsig(zo) * fmaxf(c, 0.f);
            float* own = &h_s[p ^ 1][r2][jg];
            *own = h;
            st_remote_f32(own, peer, h);
            hseq[((size_t)(b0 + r2) * TT + t) * 128 + jg] = h;
            __syncwarp();
            if (lane == 0) mbar_arrive_remote(mbar, peer);   // 1 release-arrive per warp
        }
        cp_async_wait6();
        __syncthreads();       // local half + z reuse ordering
        mbar_wait(mbar, par);  // acquire peer's 8 arrivals
        par ^= 1;
        p ^= 1;
    }
}

// ---------------- host orchestration ----------------------------------------
extern "C" void kernel_launch(void* const* d_in, const int* in_sizes, int n_in,
                              void* d_out, int out_size) {
    const float* x    = (const float*)d_in[0];
    const float* Wk1  = (const float*)d_in[1];
    const float* Wr1  = (const float*)d_in[2];
    const float* b1   = (const float*)d_in[3];
    const float* Wk2  = (const float*)d_in[4];
    const float* Wr2  = (const float*)d_in[5];
    const float* b2   = (const float*)d_in[6];
    const float* Wd1k = (const float*)d_in[7];
    const float* Wd1r = (const float*)d_in[8];
    const float* bd1  = (const float*)d_in[9];
    const float* Wd2k = (const float*)d_in[10];
    const float* Wd2r = (const float*)d_in[11];
    const float* bd2  = (const float*)d_in[12];
    const float* Wout = (const float*)d_in[13];
    const float* bout = (const float*)d_in[14];
    float* out = (float*)d_out;

    float *bufG, *h1, *d1, *d2, *z, *gd1;
    cudaGetSymbolAddress((void**)&bufG, g_bufG);
    cudaGetSymbolAddress((void**)&h1,  g_h1);
    cudaGetSymbolAddress((void**)&d1,  g_d1);
    cudaGetSymbolAddress((void**)&d2,  g_d2);
    cudaGetSymbolAddress((void**)&z,   g_z);
    cudaGetSymbolAddress((void**)&gd1, g_gd1);

    dim3 blk(256);

    // 1) G1 = x @ Wk1 + b1                     [BT,512]
    gemm_f32x2_kernel<128><<<dim3(1024, 4), blk>>>(x, Wk1, b1, bufG, BT, 512, 64);
    // 2) encoder L1 recurrence -> h1           [BT,128]
    lstm128_kernel<<<128, blk>>>(bufG, Wr1, h1);
    // 3) G2 = h1 @ Wk2 + b2                    [BT,256]
    gemm_f32x2_kernel<128><<<dim3(1024, 2), blk>>>(h1, Wk2, b2, bufG, BT, 256, 128);
    // 4) encoder L2 recurrence -> z (last h)   [256,64]
    lstm64_kernel<<<128, blk>>>(bufG, Wr2, nullptr, z, 0);
    // 5) Gd1 = z @ Wd1k + bd1 (constant/step)  [256,256]
    gemm_f32x2_kernel<128><<<dim3(2, 2), blk>>>(z, Wd1k, bd1, gd1, 256, 256, 64);
    // 6) decoder L1 recurrence -> d1           [BT,64]
    lstm64_kernel<<<128, blk>>>(gd1, Wd1r, d1, nullptr, 1);
    // 7) Gd2 = d1 @ Wd2k + bd2                 [BT,512]
    gemm_f32x2_kernel<128><<<dim3(1024, 4), blk>>>(d1, Wd2k, bd2, bufG, BT, 512, 64);
    // 8) decoder L2 recurrence -> d2           [BT,128]
    lstm128_kernel<<<128, blk>>>(bufG, Wd2r, d2);
    // 9) out = d2 @ Wout + bout                [BT,64] == [B,T,F]
    gemm_f32x2_kernel<64><<<dim3(1024, 1), blk>>>(d2, Wout, bout, out, BT, 64, 128);
}